// round 15
// baseline (speedup 1.0000x reference)
#include <cuda_runtime.h>

// Problem constants (fixed by the reference)
#define BB 1024
#define NN 16
#define TT 256
#define TPB 128                     // empirically best block size
#define GRID (BB * (TT / TPB))      // 2048 blocks, 2 per batch b

// Pair-triangle storage for an 8x8 lower block: pair s holds rows (2s, 2s+1),
// slot (s,k) = column k, k = 0..2s+1. Offset s*s+s+k, 20 slots for 4 pairs.
#define PIX(s, k) ((s) * (s) + (s) + (k))

typedef unsigned long long u64;     // one packed f32x2 (lo = even row)

// Scratch for deterministic single-launch reduction (no cudaMalloc allowed)
__device__ float g_partials[GRID];
__device__ unsigned int g_count = 0;   // self-resetting arrival counter

// ---- packed fp32x2 primitives (sm_103a; PTX-only, ptxas won't auto-fuse)
__device__ __forceinline__ u64 pack2(float lo, float hi) {
    u64 r; asm("mov.b64 %0, {%1, %2};" : "=l"(r) : "f"(lo), "f"(hi)); return r;
}
__device__ __forceinline__ void unpack2(u64 v, float& lo, float& hi) {
    asm("mov.b64 {%0, %1}, %2;" : "=f"(lo), "=f"(hi) : "l"(v));
}
__device__ __forceinline__ u64 fma2(u64 a, u64 b, u64 c) {   // a*b + c per lane
    u64 d; asm("fma.rn.f32x2 %0, %1, %2, %3;" : "=l"(d) : "l"(a), "l"(b), "l"(c));
    return d;
}
__device__ __forceinline__ u64 mul2(u64 a, u64 b) {
    u64 d; asm("mul.rn.f32x2 %0, %1, %2;" : "=l"(d) : "l"(a), "l"(b)); return d;
}

__global__ __launch_bounds__(TPB, 4) void gll_f32x2p_kernel(
    const float* __restrict__ pred,
    const float* __restrict__ targ,
    const float* __restrict__ cov,
    float* __restrict__ out)
{
    const int tid = threadIdx.x;
    const int bid = blockIdx.x;
    const int b   = bid >> 1;
    const int t   = ((bid & 1) << 7) + tid;   // this thread's time index

    // cov plane (i,j) element t at cov[((b*16+i)*16+j)*256 + t]; consecutive
    // tid -> consecutive t -> fully coalesced 128B warp runs per plane.
    const float* covb = cov + ((size_t)b * NN * NN) * TT + t;

    float pivprod = 1.0f;
    float quad    = 0.0f;

    u64 Y[8];          // paired diff vector (rows 2s, 2s+1)
    u64 T[20];         // block(0:8,0:8) lower triangle, row-pairs
    u64 G[4][8];       // block(8:16,0:8), row-pairs x 8 cols

    // ======== Front loads: y + first block-column (132 scalar LDGs) ========
#pragma unroll
    for (int s = 0; s < 8; ++s) {
        const int o0 = (b * NN + 2 * s)     * TT + t;
        const int o1 = (b * NN + 2 * s + 1) * TT + t;
        Y[s] = pack2(pred[o0] - targ[o0], pred[o1] - targ[o1]);
    }
#pragma unroll
    for (int s = 0; s < 4; ++s) {
        const int r0 = 2 * s, r1 = 2 * s + 1;
#pragma unroll
        for (int k = 0; k <= 2 * s; ++k)
            T[PIX(s, k)] = pack2(covb[(r0 * NN + k) * TT],
                                 covb[(r1 * NN + k) * TT]);
        // dead lane (.x) zeroed: row 2s < col 2s+1, never read as broadcast
        T[PIX(s, 2 * s + 1)] = pack2(0.0f, covb[(r1 * NN + (2 * s + 1)) * TT]);
    }
#pragma unroll
    for (int r = 0; r < 4; ++r)
#pragma unroll
        for (int k = 0; k < 8; ++k)
            G[r][k] = pack2(covb[((8 + 2 * r)     * NN + k) * TT],
                            covb[((8 + 2 * r + 1) * NN + k) * TT]);

    // ======== Phase 1: factor cols 0-7 over the full 16-row panel ========
    // Pivots >= 1 (Sigma = AA^T + I): rsqrt/log safe; det fits fp32.
#pragma unroll
    for (int j = 0; j < 8; ++j) {
        const int js = j >> 1, jr = j & 1;

        float pa, pb;
        unpack2(T[PIX(js, j)], pa, pb);
        const float piv = jr ? pb : pa;
        pivprod *= piv;
        const float invd  = rsqrtf(piv);
        const u64   invd2 = pack2(invd, invd);

#pragma unroll
        for (int s = js; s < 4; ++s) T[PIX(s, j)] = mul2(T[PIX(s, j)], invd2);
#pragma unroll
        for (int r = 0; r < 4; ++r)  G[r][j]      = mul2(G[r][j], invd2);

        float ya, yb;
        unpack2(Y[js], ya, yb);
        float yj;
        if (jr == 0) {
            yj = ya * invd;
            quad = fmaf(yj, yj, quad);
            float la, lb;
            unpack2(T[PIX(js, j)], la, lb);    // lb = L[j+1][j] (scaled)
            yb = fmaf(-lb, yj, yb);
            Y[js] = pack2(yj, yb);
        } else {
            yj = yb * invd;
            quad = fmaf(yj, yj, quad);
            Y[js] = pack2(ya, yj);
        }
        const u64 myj2 = pack2(-yj, -yj);
#pragma unroll
        for (int s = js + 1; s < 4; ++s) Y[s]     = fma2(T[PIX(s, j)], myj2, Y[s]);
#pragma unroll
        for (int r = 0; r < 4; ++r)      Y[4 + r] = fma2(G[r][j], myj2, Y[4 + r]);

        // trailing update within cols j+1..7 (cols 8-15 deferred to syrk)
#pragma unroll
        for (int k = j + 1; k < 8; ++k) {
            const int ks = k >> 1, kr = k & 1;
            float ca, cb;
            unpack2(T[PIX(ks, j)], ca, cb);
            const float ck  = kr ? cb : ca;    // L[k][j], row k >= col -> live
            const u64   mck = pack2(-ck, -ck);
#pragma unroll
            for (int s = ks; s < 4; ++s)
                T[PIX(s, k)] = fma2(T[PIX(s, j)], mck, T[PIX(s, k)]);
#pragma unroll
            for (int r = 0; r < 4; ++r)
                G[r][k] = fma2(G[r][j], mck, G[r][k]);
        }
    }
    // T is dead here -> its 20 u64 free up for H below (liveness-forced split:
    // ptxas cannot sink these loads without raising peak pressure).

    // ======== Mid loads: trailing 8x8 block (36 scalar LDGs) ========
    u64 H[20];         // block(8:16,8:16) lower triangle, row-pairs
#pragma unroll
    for (int s = 0; s < 4; ++s) {
        const int r0 = 8 + 2 * s, r1 = 9 + 2 * s;
#pragma unroll
        for (int c = 0; c <= 2 * s; ++c)
            H[PIX(s, c)] = pack2(covb[(r0 * NN + (8 + c)) * TT],
                                 covb[(r1 * NN + (8 + c)) * TT]);
        H[PIX(s, 2 * s + 1)] = pack2(0.0f, covb[(r1 * NN + (9 + 2 * s)) * TT]);
    }

    // ======== syrk: H -= G * G^T (lower triangle, packed rows) ========
#pragma unroll
    for (int c = 0; c < 8; ++c) {
        const int cs = c >> 1, cr = c & 1;
#pragma unroll
        for (int m = 0; m < 8; ++m) {
            float ga, gb;
            unpack2(G[cs][m], ga, gb);
            const float gc  = cr ? gb : ga;    // L[8+c][m]
            const u64   mgc = pack2(-gc, -gc);
#pragma unroll
            for (int s = cs; s < 4; ++s)       // c <= 2s+1 guaranteed
                H[PIX(s, c)] = fma2(G[s][m], mgc, H[PIX(s, c)]);
        }
    }

    // ======== Phase 2: factor cols 8-15, finish the solve ========
#pragma unroll
    for (int j = 0; j < 8; ++j) {
        const int js = j >> 1, jr = j & 1;

        float pa, pb;
        unpack2(H[PIX(js, j)], pa, pb);
        const float piv = jr ? pb : pa;
        pivprod *= piv;
        const float invd  = rsqrtf(piv);
        const u64   invd2 = pack2(invd, invd);

#pragma unroll
        for (int s = js; s < 4; ++s) H[PIX(s, j)] = mul2(H[PIX(s, j)], invd2);

        float ya, yb;
        unpack2(Y[4 + js], ya, yb);
        float yj;
        if (jr == 0) {
            yj = ya * invd;
            quad = fmaf(yj, yj, quad);
            float la, lb;
            unpack2(H[PIX(js, j)], la, lb);
            yb = fmaf(-lb, yj, yb);
            Y[4 + js] = pack2(yj, yb);
        } else {
            yj = yb * invd;
            quad = fmaf(yj, yj, quad);
            Y[4 + js] = pack2(ya, yj);
        }
        const u64 myj2 = pack2(-yj, -yj);
#pragma unroll
        for (int s = js + 1; s < 4; ++s)
            Y[4 + s] = fma2(H[PIX(s, j)], myj2, Y[4 + s]);

#pragma unroll
        for (int k = j + 1; k < 8; ++k) {
            const int ks = k >> 1, kr = k & 1;
            float ca, cb;
            unpack2(H[PIX(ks, j)], ca, cb);
            const float ck  = kr ? cb : ca;
            const u64   mck = pack2(-ck, -ck);
#pragma unroll
            for (int s = ks; s < 4; ++s)
                H[PIX(s, k)] = fma2(H[PIX(s, j)], mck, H[PIX(s, k)]);
        }
    }

    // pivprod = det(Sigma) >= 1, within fp32 range -> one __logf.
    float v = quad + __logf(pivprod);

    // ---- In-block reduction: warp shuffles + 4-warp smem combine
    const int lane = tid & 31;
    const int wid  = tid >> 5;
#pragma unroll
    for (int o = 16; o > 0; o >>= 1) v += __shfl_down_sync(0xffffffffu, v, o);

    __shared__ float warpsum[TPB / 32];
    __shared__ bool  isLast;
    if (lane == 0) warpsum[wid] = v;
    __syncthreads();

    if (tid == 0) {
        float s = warpsum[0] + warpsum[1] + warpsum[2] + warpsum[3];
        g_partials[bid] = s;
        __threadfence();
        unsigned int c = atomicAdd(&g_count, 1u);
        isLast = (c == (unsigned int)(GRID - 1));
    }
    __syncthreads();

    // Last arriving block performs the deterministic final sum (fixed order).
    if (isLast) {
        float s = 0.0f;
#pragma unroll 8
        for (int i = tid; i < GRID; i += TPB) s += g_partials[i];
#pragma unroll
        for (int o = 16; o > 0; o >>= 1) s += __shfl_down_sync(0xffffffffu, s, o);
        if (lane == 0) warpsum[wid] = s;
        __syncthreads();
        if (tid == 0) {
            out[0] = (warpsum[0] + warpsum[1] + warpsum[2] + warpsum[3])
                     * (1.0f / (float)(BB * TT));
            g_count = 0;   // reset for the next graph replay
        }
    }
}

extern "C" void kernel_launch(void* const* d_in, const int* in_sizes, int n_in,
                              void* d_out, int out_size)
{
    const float* pred = (const float*)d_in[0];   // prediction [B,N,T]
    const float* targ = (const float*)d_in[1];   // target     [B,N,T]
    const float* cov  = (const float*)d_in[2];   // cov        [B,N,N,T]
    float* out = (float*)d_out;

    gll_f32x2p_kernel<<<GRID, TPB>>>(pred, targ, cov, out);
}

// round 17
// speedup vs baseline: 2.8058x; 2.8058x over previous
#include <cuda_runtime.h>

// Problem constants (fixed by the reference)
#define BB 1024
#define NN 16
#define TT 256
#define HTT (TT / 2)                // t-pairs per batch row
#define TPB 128                     // 128 threads x 2 t-lanes = 256 t = one b
#define GRID BB                     // 1024 blocks, one per batch b

#define TRI(i, j) ((i) * ((i) + 1) / 2 + (j))   // packed 4x4 lower-tri index

typedef unsigned long long u64;     // packed f32x2: .lo = t even, .hi = t odd

// Scratch for deterministic single-launch reduction (no cudaMalloc allowed)
__device__ float g_partials[GRID];
__device__ unsigned int g_count = 0;   // self-resetting arrival counter

// ---- packed fp32x2 primitives (sm_103a; PTX-only, ptxas won't auto-fuse)
__device__ __forceinline__ u64 pack2(float lo, float hi) {
    u64 r; asm("mov.b64 %0, {%1, %2};" : "=l"(r) : "f"(lo), "f"(hi)); return r;
}
__device__ __forceinline__ void unpack2(u64 v, float& lo, float& hi) {
    asm("mov.b64 {%0, %1}, %2;" : "=f"(lo), "=f"(hi) : "l"(v));
}
__device__ __forceinline__ u64 fma2(u64 a, u64 b, u64 c) {   // a*b + c per lane
    u64 d; asm("fma.rn.f32x2 %0, %1, %2, %3;" : "=l"(d) : "l"(a), "l"(b), "l"(c));
    return d;
}
__device__ __forceinline__ u64 mul2(u64 a, u64 b) {
    u64 d; asm("mul.rn.f32x2 %0, %1, %2;" : "=l"(d) : "l"(a), "l"(b)); return d;
}
__device__ __forceinline__ u64 neg2(u64 a) {                 // flip both signs
    return a ^ 0x8000000080000000ULL;
}
__device__ __forceinline__ u64 rsqrt2(u64 v) {               // per-lane rsqrt
    float a, b; unpack2(v, a, b);
    return pack2(rsqrtf(a), rsqrtf(b));
}

// Factor a width-4 panel over packed time-lanes. T = 4x4 packed lower tri,
// R = NR x 4 rows below. Fused forward solve on y[BASE..]. Both lanes are
// independent problems; pivots >= 1 in each lane (Sigma = AA^T + I).
#define FACTOR_PANEL(T, R, NR, BASE)                                        \
    _Pragma("unroll")                                                       \
    for (int j = 0; j < 4; ++j) {                                           \
        const u64 piv2 = T[TRI(j, j)];                                      \
        pivprod2 = mul2(pivprod2, piv2);                                    \
        const u64 invd2 = rsqrt2(piv2);                                     \
        const u64 yj = mul2(y[BASE + j], invd2);                            \
        y[BASE + j] = yj;                                                   \
        quad2 = fma2(yj, yj, quad2);                                        \
        _Pragma("unroll")                                                   \
        for (int i = j + 1; i < 4; ++i) T[TRI(i, j)] = mul2(T[TRI(i, j)], invd2); \
        _Pragma("unroll")                                                   \
        for (int r = 0; r < NR; ++r) R[r][j] = mul2(R[r][j], invd2);        \
        const u64 nyj = neg2(yj);                                           \
        _Pragma("unroll")                                                   \
        for (int i = j + 1; i < 4; ++i)                                     \
            y[BASE + i] = fma2(T[TRI(i, j)], nyj, y[BASE + i]);             \
        _Pragma("unroll")                                                   \
        for (int r = 0; r < NR; ++r)                                        \
            y[BASE + 4 + r] = fma2(R[r][j], nyj, y[BASE + 4 + r]);          \
        _Pragma("unroll")                                                   \
        for (int k = j + 1; k < 4; ++k) {                                   \
            const u64 nck = neg2(T[TRI(k, j)]);                             \
            _Pragma("unroll")                                               \
            for (int i = k; i < 4; ++i)                                     \
                T[TRI(i, k)] = fma2(T[TRI(i, j)], nck, T[TRI(i, k)]);       \
            _Pragma("unroll")                                               \
            for (int r = 0; r < NR; ++r)                                    \
                R[r][k] = fma2(R[r][j], nck, R[r][k]);                      \
        }                                                                   \
    }

__global__ __launch_bounds__(TPB, 2) void gll_tpair_kernel(
    const float* __restrict__ pred,
    const float* __restrict__ targ,
    const float* __restrict__ cov,
    float* __restrict__ out)
{
    const int tid = threadIdx.x;
    const int b   = blockIdx.x;

    // u64 views: element = one t-pair (2*tid, 2*tid+1). All bases 8B-aligned
    // (every plane/row is 1024B). Warp reads 256B contiguous per plane.
    const u64* covb  = reinterpret_cast<const u64*>(cov)
                       + (size_t)b * NN * NN * HTT + tid;
    const u64* predb = reinterpret_cast<const u64*>(pred)
                       + (size_t)b * NN * HTT + tid;
    const u64* targb = reinterpret_cast<const u64*>(targ)
                       + (size_t)b * NN * HTT + tid;

    const u64 CNEG1 = 0xBF800000BF800000ULL;   // packed (-1.0f, -1.0f)
    u64 pivprod2 = 0x3F8000003F800000ULL;      // packed (1.0f, 1.0f)
    u64 quad2    = 0;                          // packed (0.0f, 0.0f)

    // ---- diff vector: y = pred - targ = targ*(-1) + pred, packed
    u64 y[NN];
#pragma unroll
    for (int i = 0; i < NN; ++i)
        y[i] = fma2(targb[i * HTT], CNEG1, predb[i * HTT]);

    // ================= Panel 1: cols 0-3 =================
    u64 T1[10];                 // rows 0-3, packed lower tri
    u64 R1[12][4];              // rows 4-15 x cols 0-3
#pragma unroll
    for (int i = 0; i < 4; ++i)
#pragma unroll
        for (int j = 0; j <= i; ++j)
            T1[TRI(i, j)] = covb[(i * NN + j) * HTT];
#pragma unroll
    for (int r = 0; r < 12; ++r)
#pragma unroll
        for (int c = 0; c < 4; ++c)
            R1[r][c] = covb[((4 + r) * NN + c) * HTT];

    FACTOR_PANEL(T1, R1, 12, 0)   // T1 dead after this

    // ================= Panel 2: cols 4-7 =================
    u64 T2[10];                 // rows 4-7 (local q), packed lower tri
    u64 R2[8][4];               // rows 8-15 (local r) x cols 4-7
#pragma unroll
    for (int q = 0; q < 4; ++q)
#pragma unroll
        for (int c = 0; c <= q; ++c)
            T2[TRI(q, c)] = covb[((4 + q) * NN + (4 + c)) * HTT];
#pragma unroll
    for (int r = 0; r < 8; ++r)
#pragma unroll
        for (int c = 0; c < 4; ++c)
            R2[r][c] = covb[((8 + r) * NN + (4 + c)) * HTT];

    // syrk update from panel 1 (L rows 4-15 live in R1)
#pragma unroll
    for (int c = 0; c < 4; ++c) {
#pragma unroll
        for (int m = 0; m < 4; ++m) {
            const u64 nl = neg2(R1[c][m]);                 // -L[4+c][m]
#pragma unroll
            for (int q = c; q < 4; ++q)
                T2[TRI(q, c)] = fma2(R1[q][m], nl, T2[TRI(q, c)]);
#pragma unroll
            for (int r = 0; r < 8; ++r)
                R2[r][c] = fma2(R1[r + 4][m], nl, R2[r][c]);
        }
    }
    FACTOR_PANEL(T2, R2, 8, 4)    // R1 rows 0-3 dead after this

    // ================= Panel 3: cols 8-11 =================
    u64 T3[10];                 // rows 8-11, packed lower tri
    u64 R3[4][4];               // rows 12-15 x cols 8-11
#pragma unroll
    for (int q = 0; q < 4; ++q)
#pragma unroll
        for (int c = 0; c <= q; ++c)
            T3[TRI(q, c)] = covb[((8 + q) * NN + (8 + c)) * HTT];
#pragma unroll
    for (int r = 0; r < 4; ++r)
#pragma unroll
        for (int c = 0; c < 4; ++c)
            R3[r][c] = covb[((12 + r) * NN + (8 + c)) * HTT];

    // updates from panel 1 (R1 rows 4..11 ~ global 8-15) and panel 2 (R2)
#pragma unroll
    for (int c = 0; c < 4; ++c) {
#pragma unroll
        for (int m = 0; m < 4; ++m) {
            const u64 nl1 = neg2(R1[c + 4][m]);            // -L[8+c][m]
#pragma unroll
            for (int q = c; q < 4; ++q)
                T3[TRI(q, c)] = fma2(R1[q + 4][m], nl1, T3[TRI(q, c)]);
#pragma unroll
            for (int r = 0; r < 4; ++r)
                R3[r][c] = fma2(R1[r + 8][m], nl1, R3[r][c]);

            const u64 nl2 = neg2(R2[c][m]);                // -L[8+c][4+m]
#pragma unroll
            for (int q = c; q < 4; ++q)
                T3[TRI(q, c)] = fma2(R2[q][m], nl2, T3[TRI(q, c)]);
#pragma unroll
            for (int r = 0; r < 4; ++r)
                R3[r][c] = fma2(R2[r + 4][m], nl2, R3[r][c]);
        }
    }
    FACTOR_PANEL(T3, R3, 4, 8)    // R1 rows 4-7, R2 rows 0-3 dead after this

    // ================= Panel 4: cols 12-15 =================
    u64 T4[10];                 // rows 12-15, packed lower tri
#pragma unroll
    for (int q = 0; q < 4; ++q)
#pragma unroll
        for (int c = 0; c <= q; ++c)
            T4[TRI(q, c)] = covb[((12 + q) * NN + (12 + c)) * HTT];

    // updates from panels 1-3 (rows 12-15: R1[8..11], R2[4..7], R3[0..3])
#pragma unroll
    for (int c = 0; c < 4; ++c) {
#pragma unroll
        for (int m = 0; m < 4; ++m) {
            const u64 nl1 = neg2(R1[c + 8][m]);
#pragma unroll
            for (int q = c; q < 4; ++q)
                T4[TRI(q, c)] = fma2(R1[q + 8][m], nl1, T4[TRI(q, c)]);
            const u64 nl2 = neg2(R2[c + 4][m]);
#pragma unroll
            for (int q = c; q < 4; ++q)
                T4[TRI(q, c)] = fma2(R2[q + 4][m], nl2, T4[TRI(q, c)]);
            const u64 nl3 = neg2(R3[c][m]);
#pragma unroll
            for (int q = c; q < 4; ++q)
                T4[TRI(q, c)] = fma2(R3[q][m], nl3, T4[TRI(q, c)]);
        }
    }
    FACTOR_PANEL(T4, R3 /*dummy, NR=0*/, 0, 12)

    // ---- finish: per-lane quad + logdet, then sum the two samples
    float qa, qb, pa, pb;
    unpack2(quad2, qa, qb);
    unpack2(pivprod2, pa, pb);      // per-lane det(Sigma) >= 1, fits fp32
    float v = (qa + __logf(pa)) + (qb + __logf(pb));

    // ---- In-block reduction: warp shuffles + 4-warp smem combine
    const int lane = tid & 31;
    const int wid  = tid >> 5;
#pragma unroll
    for (int o = 16; o > 0; o >>= 1) v += __shfl_down_sync(0xffffffffu, v, o);

    __shared__ float warpsum[TPB / 32];
    __shared__ bool  isLast;
    if (lane == 0) warpsum[wid] = v;
    __syncthreads();

    if (tid == 0) {
        float s = warpsum[0] + warpsum[1] + warpsum[2] + warpsum[3];
        g_partials[b] = s;
        __threadfence();
        unsigned int c = atomicAdd(&g_count, 1u);
        isLast = (c == (unsigned int)(GRID - 1));
    }
    __syncthreads();

    // Last arriving block performs the deterministic final sum (fixed order).
    if (isLast) {
        float s = 0.0f;
#pragma unroll 8
        for (int i = tid; i < GRID; i += TPB) s += g_partials[i];
#pragma unroll
        for (int o = 16; o > 0; o >>= 1) s += __shfl_down_sync(0xffffffffu, s, o);
        if (lane == 0) warpsum[wid] = s;
        __syncthreads();
        if (tid == 0) {
            out[0] = (warpsum[0] + warpsum[1] + warpsum[2] + warpsum[3])
                     * (1.0f / (float)(BB * TT));
            g_count = 0;   // reset for the next graph replay
        }
    }
}

extern "C" void kernel_launch(void* const* d_in, const int* in_sizes, int n_in,
                              void* d_out, int out_size)
{
    const float* pred = (const float*)d_in[0];   // prediction [B,N,T]
    const float* targ = (const float*)d_in[1];   // target     [B,N,T]
    const float* cov  = (const float*)d_in[2];   // cov        [B,N,N,T]
    float* out = (float*)d_out;

    gll_tpair_kernel<<<GRID, TPB>>>(pred, targ, cov, out);
}